// round 2
// baseline (speedup 1.0000x reference)
#include <cuda_runtime.h>

#define B_  32
#define T_  256
#define V_  32000
#define H_  512
#define G3  1536
#define ALPHA_ 1.0f

// ---------------- scratch (device globals; no allocations allowed) ----------
__device__ float g_gi0[(size_t)T_ * B_ * G3];     // [t][b][3H] layer-0 input gates
__device__ float g_h   [B_ * H_];                 // threaded hidden
__device__ float g_h1  [B_ * H_];                 // hidden after layer 0
__device__ float g_outs[(size_t)T_ * B_ * H_];    // [t][b][H] scan outputs
__device__ unsigned g_count;                      // barrier arrival count
__device__ volatile unsigned g_gen;               // barrier generation

// ---------------- packed f32x2 helpers (sm_103a FFMA2 path) ----------------
__device__ __forceinline__ unsigned long long dup2(float x) {
    unsigned long long r; asm("mov.b64 %0, {%1,%1};" : "=l"(r) : "f"(x)); return r;
}
__device__ __forceinline__ unsigned long long f2u(float x, float y) {
    unsigned long long r; asm("mov.b64 %0, {%1,%2};" : "=l"(r) : "f"(x), "f"(y)); return r;
}
__device__ __forceinline__ float2 u2f(unsigned long long v) {
    float2 f; asm("mov.b64 {%0,%1}, %2;" : "=f"(f.x), "=f"(f.y) : "l"(v)); return f;
}
__device__ __forceinline__ unsigned long long fma2(unsigned long long a,
                                                   unsigned long long b,
                                                   unsigned long long c) {
    unsigned long long d;
    asm("fma.rn.f32x2 %0, %1, %2, %3;" : "=l"(d) : "l"(a), "l"(b), "l"(c));
    return d;
}
__device__ __forceinline__ unsigned long long add2(unsigned long long a,
                                                   unsigned long long b) {
    unsigned long long d;
    asm("add.rn.f32x2 %0, %1, %2;" : "=l"(d) : "l"(a), "l"(b));
    return d;
}

__device__ __forceinline__ float sigm(float x) { return 1.f / (1.f + __expf(-x)); }

// ---------------- grid barrier (all 148 blocks co-resident, 1 wave) --------
__device__ __forceinline__ void gbar(unsigned nb) {
    __syncthreads();
    if (threadIdx.x == 0) {
        unsigned gen = g_gen;
        __threadfence();
        if (atomicAdd(&g_count, 1u) == nb - 1u) {
            g_count = 0u;
            __threadfence();
            g_gen = gen + 1u;
        } else {
            while (g_gen == gen) { }
            __threadfence();
        }
    }
    __syncthreads();
}

// ============================================================================
// GEMM (NT, K=512): MODE 0: gi0 = gather(emb, x) @ Wih0^T + bih0  (N = 1536)
//                   MODE 1: out  = outs @ Wout^T + bout           (N = 32000)
// 128x128 block, BK=16, 256 threads, 8x8 microtile, packed f32x2 accumulate.
// ============================================================================
template <int MODE>
__global__ void __launch_bounds__(256, 2)
gemm_nt(const float* __restrict__ Aemb,   // MODE0: emb
        const float* __restrict__ Bw,     // MODE0: Wih0 ; MODE1: Wout
        const float* __restrict__ bias,   // MODE0: bih0 ; MODE1: bout
        const int*   __restrict__ xtok,   // MODE0 only
        float*       __restrict__ Cout)   // MODE1 only (d_out)
{
    __shared__ float As[16][132];
    __shared__ float Bs[16][132];
    __shared__ int   rowtok[128];

    const int tid = threadIdx.x;
    const int tx  = tid & 15;
    const int ty  = tid >> 4;
    const int m0  = blockIdx.y * 128;
    const int n0  = blockIdx.x * 128;

    if (MODE == 0) {
        if (tid < 128) {
            int m = m0 + tid;
            rowtok[tid] = xtok[(m & 31) * T_ + (m >> 5)];
        }
        __syncthreads();
    }

    unsigned long long acc[8][4];
#pragma unroll
    for (int i = 0; i < 8; i++)
#pragma unroll
        for (int q = 0; q < 4; q++) acc[i][q] = 0ull;

    for (int k0 = 0; k0 < H_; k0 += 16) {
#pragma unroll
        for (int rep = 0; rep < 2; rep++) {
            int lin = tid + rep * 256;      // 0..511
            int row = lin >> 2;
            int kg  = lin & 3;
            const float* arow;
            if (MODE == 0) arow = Aemb + (size_t)rowtok[row] * H_;
            else           arow = g_outs + (size_t)(m0 + row) * H_;
            float4 va = *(const float4*)(arow + k0 + kg * 4);
            As[kg * 4 + 0][row] = va.x; As[kg * 4 + 1][row] = va.y;
            As[kg * 4 + 2][row] = va.z; As[kg * 4 + 3][row] = va.w;
            float4 vb = *(const float4*)(Bw + (size_t)(n0 + row) * H_ + k0 + kg * 4);
            Bs[kg * 4 + 0][row] = vb.x; Bs[kg * 4 + 1][row] = vb.y;
            Bs[kg * 4 + 2][row] = vb.z; Bs[kg * 4 + 3][row] = vb.w;
        }
        __syncthreads();

#pragma unroll
        for (int kk = 0; kk < 16; kk++) {
            float4 a0 = *(const float4*)&As[kk][ty * 8];
            float4 a1 = *(const float4*)&As[kk][ty * 8 + 4];
            const unsigned long long* bp = (const unsigned long long*)&Bs[kk][tx * 8];
            unsigned long long b0 = bp[0], b1 = bp[1], b2 = bp[2], b3 = bp[3];
            unsigned long long ad[8];
            ad[0] = dup2(a0.x); ad[1] = dup2(a0.y); ad[2] = dup2(a0.z); ad[3] = dup2(a0.w);
            ad[4] = dup2(a1.x); ad[5] = dup2(a1.y); ad[6] = dup2(a1.z); ad[7] = dup2(a1.w);
#pragma unroll
            for (int i = 0; i < 8; i++) {
                acc[i][0] = fma2(ad[i], b0, acc[i][0]);
                acc[i][1] = fma2(ad[i], b1, acc[i][1]);
                acc[i][2] = fma2(ad[i], b2, acc[i][2]);
                acc[i][3] = fma2(ad[i], b3, acc[i][3]);
            }
        }
        __syncthreads();
    }

    // epilogue
    float bb[8];
#pragma unroll
    for (int q = 0; q < 8; q++) bb[q] = bias[n0 + tx * 8 + q];

#pragma unroll
    for (int i = 0; i < 8; i++) {
        int m = m0 + ty * 8 + i;
        float2 c0 = u2f(acc[i][0]);
        float2 c1 = u2f(acc[i][1]);
        float2 c2 = u2f(acc[i][2]);
        float2 c3 = u2f(acc[i][3]);
        float4 o1 = make_float4((c0.x + bb[0]) * ALPHA_, (c0.y + bb[1]) * ALPHA_,
                                (c1.x + bb[2]) * ALPHA_, (c1.y + bb[3]) * ALPHA_);
        float4 o2 = make_float4((c2.x + bb[4]) * ALPHA_, (c2.y + bb[5]) * ALPHA_,
                                (c3.x + bb[6]) * ALPHA_, (c3.y + bb[7]) * ALPHA_);
        if (MODE == 0) {
            float* crow = g_gi0 + (size_t)m * G3 + n0 + tx * 8;
            *(float4*)(crow)     = o1;
            *(float4*)(crow + 4) = o2;
        } else {
            // out[b][t][v]: m = t*32 + b  ->  row = b*T + t
            size_t orow = ((size_t)((m & 31) * T_ + (m >> 5))) * V_;
            float* crow = Cout + orow + n0 + tx * 8;
            *(float4*)(crow)     = o1;
            *(float4*)(crow + 4) = o2;
        }
    }
}

// ============================================================================
// Recurrent scan: persistent kernel, 148 blocks x 256 threads, 2 gbar/step.
// Block batch-group = blockIdx&1 (16 batches), h slab staged in 32KB smem.
// Warp task = (j, 8-batch subtile); lanes split K; packed f32x2 FMA.
// ============================================================================
__global__ void __launch_bounds__(256, 1)
scan_kernel(const float* __restrict__ Whh0,
            const float* __restrict__ Wih1,
            const float* __restrict__ Whh1,
            const float* __restrict__ bih1,
            const float* __restrict__ bhh0,
            const float* __restrict__ bhh1)
{
    __shared__ float sh[16 * H_];   // 32 KB: h slab for this batch group

    const unsigned NB = gridDim.x;          // 148
    const int tid  = threadIdx.x;
    const int bid  = blockIdx.x;
    const int bg   = bid & 1;               // batch group 0/1 (batches bg*16..)
    const int lane = tid & 31;
    const int wid  = tid >> 5;
    const int wg   = (bid >> 1) * 8 + wid;  // warp id within batch group
    const int NW   = (int)(NB >> 1) * 8;    // 592 warps per group

    // zero initial hidden
    for (int i = bid * 256 + tid; i < B_ * H_; i += (int)NB * 256) g_h[i] = 0.f;
    gbar(NB);

    for (int t = 0; t < T_; t++) {
        // ---- stage h (this batch group) into smem ----
        for (int i = tid; i < 16 * H_; i += 256) sh[i] = g_h[bg * 16 * H_ + i];
        __syncthreads();

        // ---- half A: layer 0  (gh0 = h @ Whh0^T, gates, -> h1) ----
        for (int task = wg; task < 1024; task += NW) {
            int j     = task >> 1;
            int sub   = task & 1;
            int bl0   = sub * 8;           // local batch base in slab
            int ba0   = bg * 16 + bl0;     // absolute batch base
            unsigned long long aR[4], aZ[4], aN[4];
#pragma unroll
            for (int p = 0; p < 4; p++) { aR[p] = 0; aZ[p] = 0; aN[p] = 0; }

#pragma unroll 4
            for (int k = lane; k < H_; k += 32) {
                unsigned long long wr2 = dup2(Whh0[(size_t)j * H_ + k]);
                unsigned long long wz2 = dup2(Whh0[(size_t)(j + 512) * H_ + k]);
                unsigned long long wn2 = dup2(Whh0[(size_t)(j + 1024) * H_ + k]);
#pragma unroll
                for (int p = 0; p < 4; p++) {
                    unsigned long long h2 =
                        f2u(sh[(bl0 + 2 * p) * H_ + k], sh[(bl0 + 2 * p + 1) * H_ + k]);
                    aR[p] = fma2(wr2, h2, aR[p]);
                    aZ[p] = fma2(wz2, h2, aZ[p]);
                    aN[p] = fma2(wn2, h2, aN[p]);
                }
            }
#pragma unroll
            for (int p = 0; p < 4; p++)
#pragma unroll
                for (int off = 16; off > 0; off >>= 1) {
                    aR[p] = add2(aR[p], __shfl_xor_sync(0xffffffffu, aR[p], off));
                    aZ[p] = add2(aZ[p], __shfl_xor_sync(0xffffffffu, aZ[p], off));
                    aN[p] = add2(aN[p], __shfl_xor_sync(0xffffffffu, aN[p], off));
                }
            if (lane < 8) {
                int p = lane >> 1;
                float2 fr = u2f(aR[p]), fz = u2f(aZ[p]), fn = u2f(aN[p]);
                float ghr = ((lane & 1) ? fr.y : fr.x) + bhh0[j];
                float ghz = ((lane & 1) ? fz.y : fz.x) + bhh0[j + 512];
                float ghn = ((lane & 1) ? fn.y : fn.x) + bhh0[j + 1024];
                int b = ba0 + lane;
                const float* gi = g_gi0 + ((size_t)t * B_ + b) * G3;
                float r = sigm(gi[j] + ghr);
                float z = sigm(gi[j + 512] + ghz);
                float n = tanhf(gi[j + 1024] + r * ghn);
                float hold = sh[(bl0 + lane) * H_ + j];
                g_h1[(size_t)b * H_ + j] = (1.f - z) * n + z * hold;
            }
        }
        gbar(NB);

        // ---- stage h1 into smem ----
        for (int i = tid; i < 16 * H_; i += 256) sh[i] = g_h1[bg * 16 * H_ + i];
        __syncthreads();

        // ---- half B: layer 1  (both gi1 and gh1 come from h1) ----
        for (int task = wg; task < 1024; task += NW) {
            int j   = task >> 1;
            int sub = task & 1;
            int bl0 = sub * 8;
            int ba0 = bg * 16 + bl0;
            unsigned long long aIR[4], aIZ[4], aIN[4], aHR[4], aHZ[4], aHN[4];
#pragma unroll
            for (int p = 0; p < 4; p++) {
                aIR[p] = 0; aIZ[p] = 0; aIN[p] = 0;
                aHR[p] = 0; aHZ[p] = 0; aHN[p] = 0;
            }
#pragma unroll 4
            for (int k = lane; k < H_; k += 32) {
                unsigned long long wir = dup2(Wih1[(size_t)j * H_ + k]);
                unsigned long long wiz = dup2(Wih1[(size_t)(j + 512) * H_ + k]);
                unsigned long long win = dup2(Wih1[(size_t)(j + 1024) * H_ + k]);
                unsigned long long whr = dup2(Whh1[(size_t)j * H_ + k]);
                unsigned long long whz = dup2(Whh1[(size_t)(j + 512) * H_ + k]);
                unsigned long long whn = dup2(Whh1[(size_t)(j + 1024) * H_ + k]);
#pragma unroll
                for (int p = 0; p < 4; p++) {
                    unsigned long long h2 =
                        f2u(sh[(bl0 + 2 * p) * H_ + k], sh[(bl0 + 2 * p + 1) * H_ + k]);
                    aIR[p] = fma2(wir, h2, aIR[p]);
                    aIZ[p] = fma2(wiz, h2, aIZ[p]);
                    aIN[p] = fma2(win, h2, aIN[p]);
                    aHR[p] = fma2(whr, h2, aHR[p]);
                    aHZ[p] = fma2(whz, h2, aHZ[p]);
                    aHN[p] = fma2(whn, h2, aHN[p]);
                }
            }
#pragma unroll
            for (int p = 0; p < 4; p++)
#pragma unroll
                for (int off = 16; off > 0; off >>= 1) {
                    aIR[p] = add2(aIR[p], __shfl_xor_sync(0xffffffffu, aIR[p], off));
                    aIZ[p] = add2(aIZ[p], __shfl_xor_sync(0xffffffffu, aIZ[p], off));
                    aIN[p] = add2(aIN[p], __shfl_xor_sync(0xffffffffu, aIN[p], off));
                    aHR[p] = add2(aHR[p], __shfl_xor_sync(0xffffffffu, aHR[p], off));
                    aHZ[p] = add2(aHZ[p], __shfl_xor_sync(0xffffffffu, aHZ[p], off));
                    aHN[p] = add2(aHN[p], __shfl_xor_sync(0xffffffffu, aHN[p], off));
                }
            if (lane < 8) {
                int p = lane >> 1;
                int hi = lane & 1;
                float2 f;
                f = u2f(aIR[p]); float ir  = (hi ? f.y : f.x) + bih1[j];
                f = u2f(aIZ[p]); float iz  = (hi ? f.y : f.x) + bih1[j + 512];
                f = u2f(aIN[p]); float inn = (hi ? f.y : f.x) + bih1[j + 1024];
                f = u2f(aHR[p]); float hr  = (hi ? f.y : f.x) + bhh1[j];
                f = u2f(aHZ[p]); float hz  = (hi ? f.y : f.x) + bhh1[j + 512];
                f = u2f(aHN[p]); float hn  = (hi ? f.y : f.x) + bhh1[j + 1024];
                float r = sigm(ir + hr);
                float z = sigm(iz + hz);
                float n = tanhf(inn + r * hn);
                int b = ba0 + lane;
                float h1v = sh[(bl0 + lane) * H_ + j];
                float h2v = (1.f - z) * n + z * h1v;
                g_h[(size_t)b * H_ + j] = h2v;
                g_outs[((size_t)t * B_ + b) * H_ + j] = h2v;
            }
        }
        gbar(NB);
    }
}

// ============================================================================
extern "C" void kernel_launch(void* const* d_in, const int* in_sizes, int n_in,
                              void* d_out, int out_size) {
    (void)in_sizes; (void)n_in; (void)out_size;
    const int*   x    = (const int*)  d_in[0];
    const float* emb  = (const float*)d_in[1];
    const float* Wih  = (const float*)d_in[2];
    const float* Whh  = (const float*)d_in[3];
    const float* bih  = (const float*)d_in[4];
    const float* bhh  = (const float*)d_in[5];
    const float* Wout = (const float*)d_in[6];
    const float* bout = (const float*)d_in[7];
    float* out = (float*)d_out;

    // 1) gi0[t][b][:] = emb[x[b,t]] @ Wih0^T + bih0
    gemm_nt<0><<<dim3(G3 / 128, (T_ * B_) / 128), 256>>>(emb, Wih, bih, x, nullptr);

    // 2) 256-step GRU scan (persistent, grid barriers)
    scan_kernel<<<148, 256>>>(Whh,
                              Wih + (size_t)G3 * H_,
                              Whh + (size_t)G3 * H_,
                              bih + G3,
                              bhh,
                              bhh + G3);

    // 3) logits[b][t][:] = outs[t][b] @ Wout^T + bout
    gemm_nt<1><<<dim3(V_ / 128, (T_ * B_) / 128), 256>>>(nullptr, Wout, bout, nullptr, out);
}

// round 4
// speedup vs baseline: 1.5422x; 1.5422x over previous
#include <cuda_runtime.h>
#include <cuda_bf16.h>
#include <cstdint>

#define B_  32
#define T_  256
#define V_  32000
#define H_  512
#define G3  1536

// ---------------- scratch (device globals; no allocations allowed) ----------
__device__ float g_gi0[(size_t)T_ * B_ * G3];     // [t][b][3H] layer-0 input gates
__device__ float g_h   [B_ * H_];                 // threaded hidden
__device__ float g_h1  [B_ * H_];                 // hidden after layer 0
__device__ float g_outs[(size_t)T_ * B_ * H_];    // [t][b][H] scan outputs
__device__ __nv_bfloat16 g_Whi[(size_t)V_ * H_];  // Wout bf16 hi plane
__device__ __nv_bfloat16 g_Wlo[(size_t)V_ * H_];  // Wout bf16 lo plane
__device__ __nv_bfloat16 g_Ahi[(size_t)T_ * B_ * H_];
__device__ __nv_bfloat16 g_Alo[(size_t)T_ * B_ * H_];
__device__ unsigned g_count;
__device__ volatile unsigned g_gen;

// ---------------- packed f32x2 helpers -------------------------------------
__device__ __forceinline__ unsigned long long dup2(float x) {
    unsigned long long r; asm("mov.b64 %0, {%1,%1};" : "=l"(r) : "f"(x)); return r;
}
__device__ __forceinline__ unsigned long long f2u(float x, float y) {
    unsigned long long r; asm("mov.b64 %0, {%1,%2};" : "=l"(r) : "f"(x), "f"(y)); return r;
}
__device__ __forceinline__ float2 u2f(unsigned long long v) {
    float2 f; asm("mov.b64 {%0,%1}, %2;" : "=f"(f.x), "=f"(f.y) : "l"(v)); return f;
}
__device__ __forceinline__ unsigned long long fma2(unsigned long long a,
                                                   unsigned long long b,
                                                   unsigned long long c) {
    unsigned long long d;
    asm("fma.rn.f32x2 %0, %1, %2, %3;" : "=l"(d) : "l"(a), "l"(b), "l"(c));
    return d;
}
__device__ __forceinline__ unsigned long long add2(unsigned long long a,
                                                   unsigned long long b) {
    unsigned long long d;
    asm("add.rn.f32x2 %0, %1, %2;" : "=l"(d) : "l"(a), "l"(b));
    return d;
}
__device__ __forceinline__ float sigm(float x) { return 1.f / (1.f + __expf(-x)); }

__device__ __forceinline__ uint32_t smem_u32(const void* p) {
    uint32_t a;
    asm("{ .reg .u64 t; cvta.to.shared.u64 t, %1; cvt.u32.u64 %0, t; }" : "=r"(a) : "l"(p));
    return a;
}

// ---------------- mma.sync / ldmatrix / cp.async helpers --------------------
__device__ __forceinline__ void ldsm4(uint32_t* r, uint32_t addr) {
    asm volatile("ldmatrix.sync.aligned.m8n8.x4.shared.b16 {%0,%1,%2,%3}, [%4];"
        : "=r"(r[0]), "=r"(r[1]), "=r"(r[2]), "=r"(r[3]) : "r"(addr));
}
__device__ __forceinline__ void mma16816(float* c, const uint32_t* a,
                                         uint32_t b0, uint32_t b1) {
    asm volatile("mma.sync.aligned.m16n8k16.row.col.f32.bf16.bf16.f32 "
        "{%0,%1,%2,%3}, {%4,%5,%6,%7}, {%8,%9}, {%0,%1,%2,%3};"
        : "+f"(c[0]), "+f"(c[1]), "+f"(c[2]), "+f"(c[3])
        : "r"(a[0]), "r"(a[1]), "r"(a[2]), "r"(a[3]), "r"(b0), "r"(b1));
}
__device__ __forceinline__ void cpa16(uint32_t d, const void* s) {
    asm volatile("cp.async.cg.shared.global [%0], [%1], 16;" :: "r"(d), "l"(s) : "memory");
}
__device__ __forceinline__ void cpa_commit() {
    asm volatile("cp.async.commit_group;" ::: "memory");
}
template <int N>
__device__ __forceinline__ void cpa_wait() {
    asm volatile("cp.async.wait_group %0;" :: "n"(N) : "memory");
}

// ---------------- grid barrier ---------------------------------------------
__device__ __forceinline__ void gbar(unsigned nb) {
    __syncthreads();
    if (threadIdx.x == 0) {
        unsigned gen = g_gen;
        __threadfence();
        if (atomicAdd(&g_count, 1u) == nb - 1u) {
            g_count = 0u;
            __threadfence();
            g_gen = gen + 1u;
        } else {
            while (g_gen == gen) { }
            __threadfence();
        }
    }
    __syncthreads();
}

// ============================================================================
// bf16 hi/lo split converters
// ============================================================================
__global__ void conv_w(const float* __restrict__ src) {
    int i = blockIdx.x * 256 + threadIdx.x;           // per float4
    if (i >= V_ * H_ / 4) return;
    float4 v = ((const float4*)src)[i];
    __nv_bfloat16 h0 = __float2bfloat16(v.x), h1 = __float2bfloat16(v.y);
    __nv_bfloat16 h2 = __float2bfloat16(v.z), h3 = __float2bfloat16(v.w);
    __nv_bfloat162* hp = (__nv_bfloat162*)g_Whi;
    __nv_bfloat162* lp = (__nv_bfloat162*)g_Wlo;
    hp[i * 2]     = __nv_bfloat162(h0, h1);
    hp[i * 2 + 1] = __nv_bfloat162(h2, h3);
    lp[i * 2]     = __nv_bfloat162(__float2bfloat16(v.x - __bfloat162float(h0)),
                                   __float2bfloat16(v.y - __bfloat162float(h1)));
    lp[i * 2 + 1] = __nv_bfloat162(__float2bfloat16(v.z - __bfloat162float(h2)),
                                   __float2bfloat16(v.w - __bfloat162float(h3)));
}
__global__ void conv_a() {
    int i = blockIdx.x * 256 + threadIdx.x;
    if (i >= T_ * B_ * H_ / 4) return;
    float4 v = ((const float4*)g_outs)[i];
    __nv_bfloat16 h0 = __float2bfloat16(v.x), h1 = __float2bfloat16(v.y);
    __nv_bfloat16 h2 = __float2bfloat16(v.z), h3 = __float2bfloat16(v.w);
    __nv_bfloat162* hp = (__nv_bfloat162*)g_Ahi;
    __nv_bfloat162* lp = (__nv_bfloat162*)g_Alo;
    hp[i * 2]     = __nv_bfloat162(h0, h1);
    hp[i * 2 + 1] = __nv_bfloat162(h2, h3);
    lp[i * 2]     = __nv_bfloat162(__float2bfloat16(v.x - __bfloat162float(h0)),
                                   __float2bfloat16(v.y - __bfloat162float(h1)));
    lp[i * 2 + 1] = __nv_bfloat162(__float2bfloat16(v.z - __bfloat162float(h2)),
                                   __float2bfloat16(v.w - __bfloat162float(h3)));
}

// ============================================================================
// gi0 = gather(emb, x) @ Wih0^T + bih0   (SIMT GEMM, small: 12.9 GF)
// ============================================================================
__global__ void __launch_bounds__(256, 2)
gemm_gi0(const float* __restrict__ Aemb, const float* __restrict__ Bw,
         const float* __restrict__ bias, const int* __restrict__ xtok)
{
    __shared__ float As[16][132];
    __shared__ float Bs[16][132];
    __shared__ int   rowtok[128];

    const int tid = threadIdx.x;
    const int tx  = tid & 15;
    const int ty  = tid >> 4;
    const int m0  = blockIdx.y * 128;
    const int n0  = blockIdx.x * 128;

    if (tid < 128) {
        int m = m0 + tid;
        rowtok[tid] = xtok[(m & 31) * T_ + (m >> 5)];
    }
    __syncthreads();

    unsigned long long acc[8][4];
#pragma unroll
    for (int i = 0; i < 8; i++)
#pragma unroll
        for (int q = 0; q < 4; q++) acc[i][q] = 0ull;

    for (int k0 = 0; k0 < H_; k0 += 16) {
#pragma unroll
        for (int rep = 0; rep < 2; rep++) {
            int lin = tid + rep * 256;
            int row = lin >> 2;
            int kg  = lin & 3;
            float4 va = *(const float4*)(Aemb + (size_t)rowtok[row] * H_ + k0 + kg * 4);
            As[kg * 4 + 0][row] = va.x; As[kg * 4 + 1][row] = va.y;
            As[kg * 4 + 2][row] = va.z; As[kg * 4 + 3][row] = va.w;
            float4 vb = *(const float4*)(Bw + (size_t)(n0 + row) * H_ + k0 + kg * 4);
            Bs[kg * 4 + 0][row] = vb.x; Bs[kg * 4 + 1][row] = vb.y;
            Bs[kg * 4 + 2][row] = vb.z; Bs[kg * 4 + 3][row] = vb.w;
        }
        __syncthreads();

#pragma unroll
        for (int kk = 0; kk < 16; kk++) {
            float4 a0 = *(const float4*)&As[kk][ty * 8];
            float4 a1 = *(const float4*)&As[kk][ty * 8 + 4];
            const unsigned long long* bp = (const unsigned long long*)&Bs[kk][tx * 8];
            unsigned long long b0 = bp[0], b1 = bp[1], b2 = bp[2], b3 = bp[3];
            unsigned long long ad[8];
            ad[0] = dup2(a0.x); ad[1] = dup2(a0.y); ad[2] = dup2(a0.z); ad[3] = dup2(a0.w);
            ad[4] = dup2(a1.x); ad[5] = dup2(a1.y); ad[6] = dup2(a1.z); ad[7] = dup2(a1.w);
#pragma unroll
            for (int i = 0; i < 8; i++) {
                acc[i][0] = fma2(ad[i], b0, acc[i][0]);
                acc[i][1] = fma2(ad[i], b1, acc[i][1]);
                acc[i][2] = fma2(ad[i], b2, acc[i][2]);
                acc[i][3] = fma2(ad[i], b3, acc[i][3]);
            }
        }
        __syncthreads();
    }

    float bb[8];
#pragma unroll
    for (int q = 0; q < 8; q++) bb[q] = bias[n0 + tx * 8 + q];
#pragma unroll
    for (int i = 0; i < 8; i++) {
        int m = m0 + ty * 8 + i;
        float2 c0 = u2f(acc[i][0]);
        float2 c1 = u2f(acc[i][1]);
        float2 c2 = u2f(acc[i][2]);
        float2 c3 = u2f(acc[i][3]);
        float* crow = g_gi0 + (size_t)m * G3 + n0 + tx * 8;
        *(float4*)(crow)     = make_float4(c0.x + bb[0], c0.y + bb[1], c1.x + bb[2], c1.y + bb[3]);
        *(float4*)(crow + 4) = make_float4(c2.x + bb[4], c2.y + bb[5], c3.x + bb[6], c3.y + bb[7]);
    }
}

// ============================================================================
// Recurrent scan: 148 blocks x 512 threads, 4 batch-groups of 8.
// ============================================================================
__global__ void __launch_bounds__(512, 1)
scan_kernel(const float* __restrict__ Whh0,
            const float* __restrict__ Wih1,
            const float* __restrict__ Whh1,
            const float* __restrict__ bih1,
            const float* __restrict__ bhh0,
            const float* __restrict__ bhh1)
{
    __shared__ float sh[8 * H_];

    const unsigned NB = gridDim.x;          // 148
    const int tid  = threadIdx.x;
    const int bid  = blockIdx.x;
    const int bg   = bid & 3;
    const int lane = tid & 31;
    const int wid  = tid >> 5;
    const int wg   = (bid >> 2) * 16 + wid;

    for (int i = bid * 512 + tid; i < B_ * H_; i += (int)NB * 512) g_h[i] = 0.f;
    gbar(NB);

    for (int t = 0; t < T_; t++) {
        for (int i = tid; i < 8 * H_; i += 512) sh[i] = g_h[bg * 8 * H_ + i];
        __syncthreads();

        if (wg < 512) {
            const int j = wg;
            unsigned long long aR[4], aZ[4], aN[4];
#pragma unroll
            for (int p = 0; p < 4; p++) { aR[p] = 0; aZ[p] = 0; aN[p] = 0; }
#pragma unroll 4
            for (int k = lane; k < H_; k += 32) {
                unsigned long long wr2 = dup2(Whh0[(size_t)j * H_ + k]);
                unsigned long long wz2 = dup2(Whh0[(size_t)(j + 512) * H_ + k]);
                unsigned long long wn2 = dup2(Whh0[(size_t)(j + 1024) * H_ + k]);
#pragma unroll
                for (int p = 0; p < 4; p++) {
                    unsigned long long h2 = f2u(sh[(2 * p) * H_ + k], sh[(2 * p + 1) * H_ + k]);
                    aR[p] = fma2(wr2, h2, aR[p]);
                    aZ[p] = fma2(wz2, h2, aZ[p]);
                    aN[p] = fma2(wn2, h2, aN[p]);
                }
            }
#pragma unroll
            for (int p = 0; p < 4; p++)
#pragma unroll
                for (int off = 16; off > 0; off >>= 1) {
                    aR[p] = add2(aR[p], __shfl_xor_sync(0xffffffffu, aR[p], off));
                    aZ[p] = add2(aZ[p], __shfl_xor_sync(0xffffffffu, aZ[p], off));
                    aN[p] = add2(aN[p], __shfl_xor_sync(0xffffffffu, aN[p], off));
                }
            if (lane < 8) {
                int p = lane >> 1, hi = lane & 1;
                float2 fr = u2f(aR[p]), fz = u2f(aZ[p]), fn = u2f(aN[p]);
                float ghr = (hi ? fr.y : fr.x) + bhh0[j];
                float ghz = (hi ? fz.y : fz.x) + bhh0[j + 512];
                float ghn = (hi ? fn.y : fn.x) + bhh0[j + 1024];
                int b = bg * 8 + lane;
                const float* gi = g_gi0 + ((size_t)t * B_ + b) * G3;
                float r = sigm(gi[j] + ghr);
                float z = sigm(gi[j + 512] + ghz);
                float n = tanhf(gi[j + 1024] + r * ghn);
                float hold = sh[lane * H_ + j];
                g_h1[(size_t)b * H_ + j] = (1.f - z) * n + z * hold;
            }
        }
        gbar(NB);

        for (int i = tid; i < 8 * H_; i += 512) sh[i] = g_h1[bg * 8 * H_ + i];
        __syncthreads();

        if (wg < 512) {
            const int j = wg;
            unsigned long long aIR[4], aIZ[4], aIN[4], aHR[4], aHZ[4], aHN[4];
#pragma unroll
            for (int p = 0; p < 4; p++) {
                aIR[p] = 0; aIZ[p] = 0; aIN[p] = 0;
                aHR[p] = 0; aHZ[p] = 0; aHN[p] = 0;
            }
#pragma unroll 4
            for (int k = lane; k < H_; k += 32) {
                unsigned long long wir = dup2(Wih1[(size_t)j * H_ + k]);
                unsigned long long wiz = dup2(Wih1[(size_t)(j + 512) * H_ + k]);
                unsigned long long win = dup2(Wih1[(size_t)(j + 1024) * H_ + k]);
                unsigned long long whr = dup2(Whh1[(size_t)j * H_ + k]);
                unsigned long long whz = dup2(Whh1[(size_t)(j + 512) * H_ + k]);
                unsigned long long whn = dup2(Whh1[(size_t)(j + 1024) * H_ + k]);
#pragma unroll
                for (int p = 0; p < 4; p++) {
                    unsigned long long h2 = f2u(sh[(2 * p) * H_ + k], sh[(2 * p + 1) * H_ + k]);
                    aIR[p] = fma2(wir, h2, aIR[p]);
                    aIZ[p] = fma2(wiz, h2, aIZ[p]);
                    aIN[p] = fma2(win, h2, aIN[p]);
                    aHR[p] = fma2(whr, h2, aHR[p]);
                    aHZ[p] = fma2(whz, h2, aHZ[p]);
                    aHN[p] = fma2(whn, h2, aHN[p]);
                }
            }
#pragma unroll
            for (int p = 0; p < 4; p++)
#pragma unroll
                for (int off = 16; off > 0; off >>= 1) {
                    aIR[p] = add2(aIR[p], __shfl_xor_sync(0xffffffffu, aIR[p], off));
                    aIZ[p] = add2(aIZ[p], __shfl_xor_sync(0xffffffffu, aIZ[p], off));
                    aIN[p] = add2(aIN[p], __shfl_xor_sync(0xffffffffu, aIN[p], off));
                    aHR[p] = add2(aHR[p], __shfl_xor_sync(0xffffffffu, aHR[p], off));
                    aHZ[p] = add2(aHZ[p], __shfl_xor_sync(0xffffffffu, aHZ[p], off));
                    aHN[p] = add2(aHN[p], __shfl_xor_sync(0xffffffffu, aHN[p], off));
                }
            if (lane < 8) {
                int p = lane >> 1, hi = lane & 1;
                float2 f;
                f = u2f(aIR[p]); float ir  = (hi ? f.y : f.x) + bih1[j];
                f = u2f(aIZ[p]); float iz  = (hi ? f.y : f.x) + bih1[j + 512];
                f = u2f(aIN[p]); float inn = (hi ? f.y : f.x) + bih1[j + 1024];
                f = u2f(aHR[p]); float hr  = (hi ? f.y : f.x) + bhh1[j];
                f = u2f(aHZ[p]); float hz  = (hi ? f.y : f.x) + bhh1[j + 512];
                f = u2f(aHN[p]); float hn  = (hi ? f.y : f.x) + bhh1[j + 1024];
                float r = sigm(ir + hr);
                float z = sigm(iz + hz);
                float n = tanhf(inn + r * hn);
                int b = bg * 8 + lane;
                float h1v = sh[lane * H_ + j];
                float h2v = (1.f - z) * n + z * h1v;
                g_h[(size_t)b * H_ + j] = h2v;
                g_outs[((size_t)t * B_ + b) * H_ + j] = h2v;
            }
        }
        gbar(NB);
    }
}

// ============================================================================
// Projection via mma.sync bf16 hi/lo split: out[b][t][:] = outs @ Wout^T + bout
// CTA 128x128, BK=64, 8 warps (warp tile 64x32), 2-stage cp.async pipeline.
// ============================================================================
#define PST 65536   // stage stride: Ahi 16K | Alo 16K | Bhi 16K | Blo 16K

__global__ void __launch_bounds__(256, 1)
proj_mma(const float* __restrict__ bout, float* __restrict__ out)
{
    extern __shared__ char psm[];
    const int tid  = threadIdx.x;
    const int lane = tid & 31;
    const int warp = tid >> 5;
    const int wm   = warp & 1;            // 2 warps along M (64 rows each)
    const int wn   = warp >> 1;           // 4 warps along N (32 cols each)
    const int m0   = blockIdx.x * 128;    // m fastest -> B tiles shared via L2
    const int n0   = blockIdx.y * 128;
    const uint32_t sb = smem_u32(psm);

    // cp.async mapping: thread -> (row, 4 x 16B chunks)
    const int lr = tid >> 1;              // row 0..127
    const int cb = (tid & 1) * 4;         // c16 base (0 or 4)

    // ldmatrix per-lane constants
    const int lrA = lane & 15;
    const int lch = lane >> 4;            // 0/1 -> +16B
    const int lx  = lrA & 7;              // swizzle xor factor

    float acc[4][4][4];
#pragma unroll
    for (int a = 0; a < 4; a++)
#pragma unroll
        for (int b = 0; b < 4; b++)
#pragma unroll
            for (int c = 0; c < 4; c++) acc[a][b][c] = 0.f;

    const __nv_bfloat16* srcAh = g_Ahi + (size_t)(m0 + lr) * H_ + cb * 8;
    const __nv_bfloat16* srcAl = g_Alo + (size_t)(m0 + lr) * H_ + cb * 8;
    const __nv_bfloat16* srcBh = g_Whi + (size_t)(n0 + lr) * H_ + cb * 8;
    const __nv_bfloat16* srcBl = g_Wlo + (size_t)(n0 + lr) * H_ + cb * 8;
    const uint32_t drow = sb + lr * 128;

#define ISSUE(kc, s) do {                                                      \
        int k0 = (kc) * 64;                                                    \
        uint32_t stb = drow + (s) * PST;                                       \
        _Pragma("unroll")                                                      \
        for (int c = 0; c < 4; c++) {                                          \
            uint32_t dsw = stb + (uint32_t)(((cb + c) ^ (lr & 7)) << 4);       \
            cpa16(dsw,         srcAh + k0 + c * 8);                            \
            cpa16(dsw + 16384, srcAl + k0 + c * 8);                            \
            cpa16(dsw + 32768, srcBh + k0 + c * 8);                            \
            cpa16(dsw + 49152, srcBl + k0 + c * 8);                            \
        }                                                                      \
        cpa_commit();                                                          \
    } while (0)

    ISSUE(0, 0);

    for (int kc = 0; kc < 8; kc++) {
        if (kc < 7) { ISSUE(kc + 1, (kc + 1) & 1); cpa_wait<1>(); }
        else        { cpa_wait<0>(); }
        __syncthreads();

        const int s = kc & 1;
        const uint32_t aRowH = sb + s * PST + (wm * 64 + lrA) * 128;
        const uint32_t aRowL = aRowH + 16384;
        const uint32_t bRowH = sb + s * PST + 32768 + (wn * 32 + lrA) * 128;
        const uint32_t bRowL = bRowH + 16384;

#pragma unroll
        for (int k16 = 0; k16 < 4; k16++) {
            const uint32_t csw = (uint32_t)(((k16 * 2 + lch) ^ lx) << 4);
            uint32_t ah[4][4], al[4][4], bh[2][4], bl[2][4];
#pragma unroll
            for (int fm = 0; fm < 4; fm++) {
                ldsm4(ah[fm], aRowH + fm * 2048 + csw);
                ldsm4(al[fm], aRowL + fm * 2048 + csw);
            }
#pragma unroll
            for (int pr = 0; pr < 2; pr++) {
                ldsm4(bh[pr], bRowH + pr * 2048 + csw);
                ldsm4(bl[pr], bRowL + pr * 2048 + csw);
            }
#pragma unroll
            for (int fm = 0; fm < 4; fm++)
#pragma unroll
                for (int pr = 0; pr < 2; pr++)
#pragma unroll
                    for (int su = 0; su < 2; su++) {
                        float* c = acc[fm][pr * 2 + su];
                        mma16816(c, ah[fm], bh[pr][su], bh[pr][su + 2]);
                        mma16816(c, ah[fm], bl[pr][su], bl[pr][su + 2]);
                        mma16816(c, al[fm], bh[pr][su], bh[pr][su + 2]);
                    }
        }
        __syncthreads();
    }

    // ---- epilogue: direct STG (32B-sector aligned float2 per lane) ----
    const int qr = lane >> 2;
    const int qc = (lane & 3) * 2;
#pragma unroll
    for (int fm = 0; fm < 4; fm++) {
        int mA = m0 + wm * 64 + fm * 16 + qr;
        int mB = mA + 8;
        size_t rowA = (size_t)((mA & 31) * T_ + (mA >> 5)) * V_;
        size_t rowB = (size_t)((mB & 31) * T_ + (mB >> 5)) * V_;
#pragma unroll
        for (int fn = 0; fn < 4; fn++) {
            int n = n0 + wn * 32 + fn * 8 + qc;
            float2 bb = *(const float2*)(bout + n);
            float* c = acc[fm][fn];
            *(float2*)(out + rowA + n) = make_float2(c[0] + bb.x, c[1] + bb.y);
            *(float2*)(out + rowB + n) = make_float2(c[2] + bb.x, c[3] + bb.y);
        }
    }
}

// ============================================================================
extern "C" void kernel_launch(void* const* d_in, const int* in_sizes, int n_in,
                              void* d_out, int out_size) {
    (void)in_sizes; (void)n_in; (void)out_size;
    const int*   x    = (const int*)  d_in[0];
    const float* emb  = (const float*)d_in[1];
    const float* Wih  = (const float*)d_in[2];
    const float* Whh  = (const float*)d_in[3];
    const float* bih  = (const float*)d_in[4];
    const float* bhh  = (const float*)d_in[5];
    const float* Wout = (const float*)d_in[6];
    const float* bout = (const float*)d_in[7];
    float* out = (float*)d_out;

    cudaFuncSetAttribute(proj_mma, cudaFuncAttributeMaxDynamicSharedMemorySize, 2 * PST);

    // 0) Wout -> bf16 hi/lo planes
    conv_w<<<(V_ * H_ / 4 + 255) / 256, 256>>>(Wout);

    // 1) gi0 = gather(emb, x) @ Wih0^T + bih0
    gemm_gi0<<<dim3(G3 / 128, (T_ * B_) / 128), 256>>>(emb, Wih, bih, x);

    // 2) 256-step GRU scan (persistent, grid barriers)
    scan_kernel<<<148, 512>>>(Whh,
                              Wih + (size_t)G3 * H_,
                              Whh + (size_t)G3 * H_,
                              bih + G3,
                              bhh,
                              bhh + G3);

    // 3) outs -> bf16 hi/lo planes
    conv_a<<<(T_ * B_ * H_ / 4 + 255) / 256, 256>>>();

    // 4) logits = outs @ Wout^T + bout  (mma.sync bf16 hi/lo split)
    proj_mma<<<dim3((T_ * B_) / 128, V_ / 128), 256, 2 * PST>>>(bout, out);
}